// round 1
// baseline (speedup 1.0000x reference)
#include <cuda_runtime.h>
#include <math.h>

// Problem constants
#define Bv   4
#define Sv   2048
#define Dv   512
#define Hv   8
#define Ev   4
#define HDv  64
#define Mv   (Bv * Sv)     // 8192
#define DEv  (Dv * Ev)     // 2048

// Scratch (device globals; no allocation allowed)
__device__ float g_q [Mv * Dv];
__device__ float g_k [Mv * Dv];
__device__ float g_v [Mv * Dv];
__device__ float g_o [Mv * Dv];
__device__ float g_x1[Mv * Dv];
__device__ float g_h [Mv * DEv];

// ---------------------------------------------------------------------------
// Generic tiled fp32 GEMM: C = epilogue(alpha * A @ B)
// A: [M,K] row-major, B: [K,N] row-major, C: [M,N] row-major
// 128x128 block tile, BK=16, 256 threads, 8x8 per-thread tile.
// ---------------------------------------------------------------------------
#define GBM 128
#define GBN 128
#define GBK 16

enum { EP_NONE = 0, EP_RES = 1, EP_BIAS_GELU = 2, EP_BIAS_RES = 3 };

__device__ __forceinline__ float gelu_tanh(float x) {
    float x3 = x * x * x;
    float t = tanhf(0.7978845608028654f * (x + 0.044715f * x3));
    return 0.5f * x * (1.0f + t);
}

template <int EPI>
__global__ __launch_bounds__(256)
void gemm_kern(const float* __restrict__ A, const float* __restrict__ Bw,
               const float* __restrict__ bias, const float* __restrict__ res,
               float* __restrict__ C, int M, int N, int K, float alpha)
{
    __shared__ float As[GBM * (GBK + 1)];
    __shared__ float Bs[GBK * GBN];

    const int tid = threadIdx.x;
    const int tx = tid & 15;       // 0..15  (N direction)
    const int ty = tid >> 4;       // 0..15  (M direction)
    const int bm = blockIdx.y * GBM;
    const int bn = blockIdx.x * GBN;

    float acc[8][8];
#pragma unroll
    for (int i = 0; i < 8; i++)
#pragma unroll
        for (int j = 0; j < 8; j++) acc[i][j] = 0.0f;

    for (int k0 = 0; k0 < K; k0 += GBK) {
        // Stage A tile: 128 x 16 = 512 float4
#pragma unroll
        for (int it = 0; it < 2; it++) {
            int idx = it * 256 + tid;           // 0..511
            int r = idx >> 2;                   // 4 float4 per row
            int c = (idx & 3) * 4;
            float4 va = *(const float4*)(A + (size_t)(bm + r) * K + k0 + c);
            float* dst = &As[r * (GBK + 1) + c];
            dst[0] = va.x; dst[1] = va.y; dst[2] = va.z; dst[3] = va.w;
        }
        // Stage B tile: 16 x 128 = 512 float4
#pragma unroll
        for (int it = 0; it < 2; it++) {
            int idx = it * 256 + tid;
            int r = idx >> 5;                   // 32 float4 per row
            int c = (idx & 31) * 4;
            *(float4*)&Bs[r * GBN + c] =
                *(const float4*)(Bw + (size_t)(k0 + r) * N + bn + c);
        }
        __syncthreads();

#pragma unroll
        for (int kk = 0; kk < GBK; kk++) {
            float a[8], b[8];
#pragma unroll
            for (int i = 0; i < 8; i++) a[i] = As[(ty * 8 + i) * (GBK + 1) + kk];
#pragma unroll
            for (int j = 0; j < 8; j++) b[j] = Bs[kk * GBN + tx * 8 + j];
#pragma unroll
            for (int i = 0; i < 8; i++)
#pragma unroll
                for (int j = 0; j < 8; j++)
                    acc[i][j] = fmaf(a[i], b[j], acc[i][j]);
        }
        __syncthreads();
    }

    // Epilogue
#pragma unroll
    for (int i = 0; i < 8; i++) {
        int row = bm + ty * 8 + i;
#pragma unroll
        for (int j = 0; j < 8; j++) {
            int col = bn + tx * 8 + j;
            float vacc = acc[i][j] * alpha;
            if (EPI == EP_BIAS_GELU || EPI == EP_BIAS_RES) vacc += bias[col];
            if (EPI == EP_BIAS_GELU) vacc = gelu_tanh(vacc);
            if (EPI == EP_RES || EPI == EP_BIAS_RES) vacc += res[(size_t)row * N + col];
            C[(size_t)row * N + col] = vacc;
        }
    }
}

// ---------------------------------------------------------------------------
// Flash attention (fp32). q,k,v stored as [B*S, D] row-major with the head
// slice at column h*HD. Scale already folded into q and k.
// One CTA: one (b,h) pair, 64 query rows. 256 threads, 4x4 per-thread tile.
// smem: Qs[64][65], Ks[64][65], Vs[64][64], Ps[64][65]  (~66 KB dynamic)
// ---------------------------------------------------------------------------
#define ATTN_SMEM ((64 * 65 * 3 + 64 * 64) * (int)sizeof(float))

__global__ __launch_bounds__(256)
void attn_kern(const float* __restrict__ q, const float* __restrict__ k,
               const float* __restrict__ v, float* __restrict__ o)
{
    extern __shared__ float sm[];
    float* Qs = sm;                 // 64*65
    float* Ks = Qs + 64 * 65;       // 64*65
    float* Ps = Ks + 64 * 65;       // 64*65
    float* Vs = Ps + 64 * 65;       // 64*64

    const int tid = threadIdx.x;
    const int tx = tid & 15;        // key-col / hd-col direction
    const int ty = tid >> 4;        // query-row direction
    const int qt = blockIdx.x;      // query tile (0..31)
    const int h  = blockIdx.y;
    const int b  = blockIdx.z;

    const float* qb = q + (size_t)b * Sv * Dv + (size_t)qt * 64 * Dv + h * HDv;
    const float* kb = k + (size_t)b * Sv * Dv + h * HDv;
    const float* vb = v + (size_t)b * Sv * Dv + h * HDv;

    // Load Q tile: 64 rows x 64 cols = 1024 float4
#pragma unroll
    for (int it = 0; it < 4; it++) {
        int idx = it * 256 + tid;
        int r = idx >> 4;
        int c = (idx & 15) * 4;
        float4 vq = *(const float4*)(qb + (size_t)r * Dv + c);
        float* dst = &Qs[r * 65 + c];
        dst[0] = vq.x; dst[1] = vq.y; dst[2] = vq.z; dst[3] = vq.w;
    }

    float mrow[4], lrow[4], oa[4][4];
#pragma unroll
    for (int i = 0; i < 4; i++) {
        mrow[i] = -1e30f;
        lrow[i] = 0.0f;
#pragma unroll
        for (int j = 0; j < 4; j++) oa[i][j] = 0.0f;
    }

    for (int kt = 0; kt < Sv / 64; kt++) {
        const float* kp = kb + (size_t)kt * 64 * Dv;
        const float* vp = vb + (size_t)kt * 64 * Dv;
#pragma unroll
        for (int it = 0; it < 4; it++) {
            int idx = it * 256 + tid;
            int r = idx >> 4;
            int c = (idx & 15) * 4;
            float4 vk = *(const float4*)(kp + (size_t)r * Dv + c);
            float* dk = &Ks[r * 65 + c];
            dk[0] = vk.x; dk[1] = vk.y; dk[2] = vk.z; dk[3] = vk.w;
            *(float4*)&Vs[r * 64 + c] = *(const float4*)(vp + (size_t)r * Dv + c);
        }
        __syncthreads();   // also guards prior-iteration Ps/Vs reads

        // S = Q @ K^T  (4x4 per thread)
        float s[4][4];
#pragma unroll
        for (int i = 0; i < 4; i++)
#pragma unroll
            for (int j = 0; j < 4; j++) s[i][j] = 0.0f;
#pragma unroll
        for (int d = 0; d < HDv; d++) {
            float a[4], bb[4];
#pragma unroll
            for (int i = 0; i < 4; i++) a[i] = Qs[(ty * 4 + i) * 65 + d];
#pragma unroll
            for (int j = 0; j < 4; j++) bb[j] = Ks[(tx * 4 + j) * 65 + d];
#pragma unroll
            for (int i = 0; i < 4; i++)
#pragma unroll
                for (int j = 0; j < 4; j++)
                    s[i][j] = fmaf(a[i], bb[j], s[i][j]);
        }

        // Online softmax update; row = 16 lanes sharing ty (tx = lane%16)
#pragma unroll
        for (int i = 0; i < 4; i++) {
            float mx = fmaxf(fmaxf(s[i][0], s[i][1]), fmaxf(s[i][2], s[i][3]));
#pragma unroll
            for (int off = 8; off > 0; off >>= 1)
                mx = fmaxf(mx, __shfl_xor_sync(0xffffffffu, mx, off));
            float mn = fmaxf(mrow[i], mx);
            float corr = __expf(mrow[i] - mn);
            float psum = 0.0f;
#pragma unroll
            for (int j = 0; j < 4; j++) {
                s[i][j] = __expf(s[i][j] - mn);
                psum += s[i][j];
            }
#pragma unroll
            for (int off = 8; off > 0; off >>= 1)
                psum += __shfl_xor_sync(0xffffffffu, psum, off);
            lrow[i] = lrow[i] * corr + psum;
            mrow[i] = mn;
#pragma unroll
            for (int j = 0; j < 4; j++) {
                oa[i][j] *= corr;
                Ps[(ty * 4 + i) * 65 + tx * 4 + j] = s[i][j];
            }
        }
        __syncthreads();

        // O += P @ V
#pragma unroll
        for (int kk = 0; kk < 64; kk++) {
            float pv[4], vv[4];
#pragma unroll
            for (int i = 0; i < 4; i++) pv[i] = Ps[(ty * 4 + i) * 65 + kk];
#pragma unroll
            for (int j = 0; j < 4; j++) vv[j] = Vs[kk * 64 + tx * 4 + j];
#pragma unroll
            for (int i = 0; i < 4; i++)
#pragma unroll
                for (int j = 0; j < 4; j++)
                    oa[i][j] = fmaf(pv[i], vv[j], oa[i][j]);
        }
        __syncthreads();
    }

    // Write O (normalized) back to [B,S,D] layout
    float* ob = o + (size_t)b * Sv * Dv + (size_t)qt * 64 * Dv + h * HDv;
#pragma unroll
    for (int i = 0; i < 4; i++) {
        float inv_l = 1.0f / lrow[i];
#pragma unroll
        for (int j = 0; j < 4; j++)
            ob[(size_t)(ty * 4 + i) * Dv + tx * 4 + j] = oa[i][j] * inv_l;
    }
}

// ---------------------------------------------------------------------------
// Launch
// ---------------------------------------------------------------------------
extern "C" void kernel_launch(void* const* d_in, const int* in_sizes, int n_in,
                              void* d_out, int out_size)
{
    const float* x  = (const float*)d_in[0];
    const float* Wq = (const float*)d_in[1];
    const float* Wk = (const float*)d_in[2];
    const float* Wv = (const float*)d_in[3];
    const float* Wo = (const float*)d_in[4];
    const float* W1 = (const float*)d_in[5];
    const float* b1 = (const float*)d_in[6];
    const float* W2 = (const float*)d_in[7];
    const float* b2 = (const float*)d_in[8];
    float* out = (float*)d_out;

    float *q, *k, *v, *o, *x1, *hbuf;
    cudaGetSymbolAddress((void**)&q,    g_q);
    cudaGetSymbolAddress((void**)&k,    g_k);
    cudaGetSymbolAddress((void**)&v,    g_v);
    cudaGetSymbolAddress((void**)&o,    g_o);
    cudaGetSymbolAddress((void**)&x1,   g_x1);
    cudaGetSymbolAddress((void**)&hbuf, g_h);

    const float scale = 0.21022410381342865f;  // 512^(-0.25)
    dim3 blk(256);
    dim3 gD (Dv  / GBN, Mv / GBM);   // (4, 64)
    dim3 gDE(DEv / GBN, Mv / GBM);   // (16, 64)

    // QKV projections (scale folded into q and k)
    gemm_kern<EP_NONE><<<gD, blk>>>(x, Wq, nullptr, nullptr, q, Mv, Dv, Dv, scale);
    gemm_kern<EP_NONE><<<gD, blk>>>(x, Wk, nullptr, nullptr, k, Mv, Dv, Dv, scale);
    gemm_kern<EP_NONE><<<gD, blk>>>(x, Wv, nullptr, nullptr, v, Mv, Dv, Dv, 1.0f);

    // Attention
    cudaFuncSetAttribute(attn_kern, cudaFuncAttributeMaxDynamicSharedMemorySize,
                         ATTN_SMEM);
    attn_kern<<<dim3(Sv / 64, Hv, Bv), blk, ATTN_SMEM>>>(q, k, v, o);

    // x1 = o @ Wo + x
    gemm_kern<EP_RES><<<gD, blk>>>(o, Wo, nullptr, x, x1, Mv, Dv, Dv, 1.0f);
    // h = gelu(x1 @ W1 + b1)
    gemm_kern<EP_BIAS_GELU><<<gDE, blk>>>(x1, W1, b1, nullptr, hbuf, Mv, DEv, Dv, 1.0f);
    // out = h @ W2 + b2 + x1
    gemm_kern<EP_BIAS_RES><<<gD, blk>>>(hbuf, W2, b2, x1, out, Mv, Dv, DEv, 1.0f);
}

// round 3
// speedup vs baseline: 1.7673x; 1.7673x over previous
#include <cuda_runtime.h>
#include <math.h>
#include <stdint.h>

// Problem constants
#define Bv   4
#define Sv   2048
#define Dv   512
#define Hv   8
#define Ev   4
#define HDv  64
#define Mv   (Bv * Sv)     // 8192
#define DEv  (Dv * Ev)     // 2048

// Scratch (device globals; no allocation allowed)
__device__ float g_q [Mv * Dv];
__device__ float g_k [Mv * Dv];
__device__ float g_v [Mv * Dv];
__device__ float g_o [Mv * Dv];
__device__ float g_x1[Mv * Dv];
__device__ float g_h [Mv * DEv];

enum { EP_NONE = 0, EP_RES = 1, EP_BIAS_GELU = 2, EP_BIAS_RES = 3 };

__device__ __forceinline__ float gelu_tanh(float x) {
    float x3 = x * x * x;
    float t = tanhf(0.7978845608028654f * (x + 0.044715f * x3));
    return 0.5f * x * (1.0f + t);
}

__device__ __forceinline__ uint32_t f2tf32(float x) {
    uint32_t r;
    asm("cvt.rna.tf32.f32 %0, %1;" : "=r"(r) : "f"(x));
    return r;
}

__device__ __forceinline__ void mma_tf32(float c[4], uint32_t a0, uint32_t a1,
                                         uint32_t a2, uint32_t a3,
                                         uint32_t b0, uint32_t b1) {
    asm volatile(
        "mma.sync.aligned.m16n8k8.row.col.f32.tf32.tf32.f32 "
        "{%0,%1,%2,%3}, {%4,%5,%6,%7}, {%8,%9}, {%0,%1,%2,%3};"
        : "+f"(c[0]), "+f"(c[1]), "+f"(c[2]), "+f"(c[3])
        : "r"(a0), "r"(a1), "r"(a2), "r"(a3), "r"(b0), "r"(b1));
}

// ---------------------------------------------------------------------------
// mma.sync tf32 GEMM: C = epilogue(alpha * A @ B)
// A: [M,K] row-major fp32, B: [K,N] row-major fp32, C: [M,N] row-major fp32
// CTA 128x128, BK=16, 256 threads. Warp grid 4(M)x2(N); warp tile 32x64.
// SMEM staged as tf32 bits. As stride 20, Bs stride 136 (conflict-free LDS).
// ---------------------------------------------------------------------------
#define AS_STRIDE 20
#define BS_STRIDE 136

template <int EPI>
__global__ __launch_bounds__(256)
void gemm_mma(const float* __restrict__ A, const float* __restrict__ Bw,
              const float* __restrict__ bias, const float* __restrict__ res,
              float* __restrict__ C, int M, int N, int K, float alpha)
{
    __shared__ uint32_t As[128 * AS_STRIDE];
    __shared__ uint32_t Bs[16 * BS_STRIDE];

    const int tid = threadIdx.x;
    const int wid = tid >> 5;
    const int lid = tid & 31;
    const int gid = lid >> 2;          // 0..7
    const int tq  = lid & 3;           // 0..3
    const int wm  = (wid >> 1) * 32;   // warp M offset in tile
    const int wn  = (wid & 1) * 64;    // warp N offset in tile
    const int bm  = blockIdx.y * 128;
    const int bn  = blockIdx.x * 128;

    float acc[2][8][4];
#pragma unroll
    for (int mt = 0; mt < 2; mt++)
#pragma unroll
        for (int nt = 0; nt < 8; nt++)
#pragma unroll
            for (int u = 0; u < 4; u++) acc[mt][nt][u] = 0.0f;

    for (int k0 = 0; k0 < K; k0 += 16) {
        // Stage A tile: 128 rows x 16 cols = 512 float4
#pragma unroll
        for (int it = 0; it < 2; it++) {
            int idx = it * 256 + tid;
            int r = idx >> 2;
            int c = (idx & 3) * 4;
            float4 v = *(const float4*)(A + (size_t)(bm + r) * K + k0 + c);
            uint32_t* dst = &As[r * AS_STRIDE + c];
            dst[0] = f2tf32(v.x); dst[1] = f2tf32(v.y);
            dst[2] = f2tf32(v.z); dst[3] = f2tf32(v.w);
        }
        // Stage B tile: 16 rows x 128 cols = 512 float4
#pragma unroll
        for (int it = 0; it < 2; it++) {
            int idx = it * 256 + tid;
            int r = idx >> 5;
            int c = (idx & 31) * 4;
            float4 v = *(const float4*)(Bw + (size_t)(k0 + r) * N + bn + c);
            uint32_t* dst = &Bs[r * BS_STRIDE + c];
            dst[0] = f2tf32(v.x); dst[1] = f2tf32(v.y);
            dst[2] = f2tf32(v.z); dst[3] = f2tf32(v.w);
        }
        __syncthreads();

#pragma unroll
        for (int ks = 0; ks < 2; ks++) {
            uint32_t bfr[8][2];
#pragma unroll
            for (int nt = 0; nt < 8; nt++) {
                bfr[nt][0] = Bs[(ks * 8 + tq)     * BS_STRIDE + wn + nt * 8 + gid];
                bfr[nt][1] = Bs[(ks * 8 + tq + 4) * BS_STRIDE + wn + nt * 8 + gid];
            }
#pragma unroll
            for (int mt = 0; mt < 2; mt++) {
                const int r0 = wm + mt * 16 + gid;
                uint32_t a0 = As[r0       * AS_STRIDE + ks * 8 + tq];
                uint32_t a1 = As[(r0 + 8) * AS_STRIDE + ks * 8 + tq];
                uint32_t a2 = As[r0       * AS_STRIDE + ks * 8 + tq + 4];
                uint32_t a3 = As[(r0 + 8) * AS_STRIDE + ks * 8 + tq + 4];
#pragma unroll
                for (int nt = 0; nt < 8; nt++)
                    mma_tf32(acc[mt][nt], a0, a1, a2, a3, bfr[nt][0], bfr[nt][1]);
            }
        }
        __syncthreads();
    }

    // Epilogue: thread owns cols 2*tq, 2*tq+1 at rows gid, gid+8 per tile
#pragma unroll
    for (int mt = 0; mt < 2; mt++) {
#pragma unroll
        for (int half = 0; half < 2; half++) {
            const int row = bm + wm + mt * 16 + gid + half * 8;
            float* Crow = C + (size_t)row * N;
            const float* rrow = (EPI == EP_RES || EPI == EP_BIAS_RES)
                                    ? (res + (size_t)row * N) : nullptr;
#pragma unroll
            for (int nt = 0; nt < 8; nt++) {
                const int col = bn + wn + nt * 8 + 2 * tq;
                float v0 = acc[mt][nt][half * 2 + 0] * alpha;
                float v1 = acc[mt][nt][half * 2 + 1] * alpha;
                if (EPI == EP_BIAS_GELU || EPI == EP_BIAS_RES) {
                    v0 += bias[col]; v1 += bias[col + 1];
                }
                if (EPI == EP_BIAS_GELU) { v0 = gelu_tanh(v0); v1 = gelu_tanh(v1); }
                if (EPI == EP_RES || EPI == EP_BIAS_RES) {
                    v0 += rrow[col]; v1 += rrow[col + 1];
                }
                *(float2*)(Crow + col) = make_float2(v0, v1);
            }
        }
    }
}

// ---------------------------------------------------------------------------
// Flash attention (fp32 SIMT) — unchanged
// ---------------------------------------------------------------------------
#define ATTN_SMEM ((64 * 65 * 3 + 64 * 64) * (int)sizeof(float))

__global__ __launch_bounds__(256)
void attn_kern(const float* __restrict__ q, const float* __restrict__ k,
               const float* __restrict__ v, float* __restrict__ o)
{
    extern __shared__ float sm[];
    float* Qs = sm;
    float* Ks = Qs + 64 * 65;
    float* Ps = Ks + 64 * 65;
    float* Vs = Ps + 64 * 65;

    const int tid = threadIdx.x;
    const int tx = tid & 15;
    const int ty = tid >> 4;
    const int qt = blockIdx.x;
    const int h  = blockIdx.y;
    const int b  = blockIdx.z;

    const float* qb = q + (size_t)b * Sv * Dv + (size_t)qt * 64 * Dv + h * HDv;
    const float* kb = k + (size_t)b * Sv * Dv + h * HDv;
    const float* vb = v + (size_t)b * Sv * Dv + h * HDv;

#pragma unroll
    for (int it = 0; it < 4; it++) {
        int idx = it * 256 + tid;
        int r = idx >> 4;
        int c = (idx & 15) * 4;
        float4 vq = *(const float4*)(qb + (size_t)r * Dv + c);
        float* dst = &Qs[r * 65 + c];
        dst[0] = vq.x; dst[1] = vq.y; dst[2] = vq.z; dst[3] = vq.w;
    }

    float mrow[4], lrow[4], oa[4][4];
#pragma unroll
    for (int i = 0; i < 4; i++) {
        mrow[i] = -1e30f;
        lrow[i] = 0.0f;
#pragma unroll
        for (int j = 0; j < 4; j++) oa[i][j] = 0.0f;
    }

    for (int kt = 0; kt < Sv / 64; kt++) {
        const float* kp = kb + (size_t)kt * 64 * Dv;
        const float* vp = vb + (size_t)kt * 64 * Dv;
#pragma unroll
        for (int it = 0; it < 4; it++) {
            int idx = it * 256 + tid;
            int r = idx >> 4;
            int c = (idx & 15) * 4;
            float4 vk = *(const float4*)(kp + (size_t)r * Dv + c);
            float* dk = &Ks[r * 65 + c];
            dk[0] = vk.x; dk[1] = vk.y; dk[2] = vk.z; dk[3] = vk.w;
            *(float4*)&Vs[r * 64 + c] = *(const float4*)(vp + (size_t)r * Dv + c);
        }
        __syncthreads();

        float s[4][4];
#pragma unroll
        for (int i = 0; i < 4; i++)
#pragma unroll
            for (int j = 0; j < 4; j++) s[i][j] = 0.0f;
#pragma unroll
        for (int d = 0; d < HDv; d++) {
            float a[4], bb[4];
#pragma unroll
            for (int i = 0; i < 4; i++) a[i] = Qs[(ty * 4 + i) * 65 + d];
#pragma unroll
            for (int j = 0; j < 4; j++) bb[j] = Ks[(tx * 4 + j) * 65 + d];
#pragma unroll
            for (int i = 0; i < 4; i++)
#pragma unroll
                for (int j = 0; j < 4; j++)
                    s[i][j] = fmaf(a[i], bb[j], s[i][j]);
        }

#pragma unroll
        for (int i = 0; i < 4; i++) {
            float mx = fmaxf(fmaxf(s[i][0], s[i][1]), fmaxf(s[i][2], s[i][3]));
#pragma unroll
            for (int off = 8; off > 0; off >>= 1)
                mx = fmaxf(mx, __shfl_xor_sync(0xffffffffu, mx, off));
            float mn = fmaxf(mrow[i], mx);
            float corr = __expf(mrow[i] - mn);
            float psum = 0.0f;
#pragma unroll
            for (int j = 0; j < 4; j++) {
                s[i][j] = __expf(s[i][j] - mn);
                psum += s[i][j];
            }
#pragma unroll
            for (int off = 8; off > 0; off >>= 1)
                psum += __shfl_xor_sync(0xffffffffu, psum, off);
            lrow[i] = lrow[i] * corr + psum;
            mrow[i] = mn;
#pragma unroll
            for (int j = 0; j < 4; j++) {
                oa[i][j] *= corr;
                Ps[(ty * 4 + i) * 65 + tx * 4 + j] = s[i][j];
            }
        }
        __syncthreads();

#pragma unroll
        for (int kk = 0; kk < 64; kk++) {
            float pv[4], vv[4];
#pragma unroll
            for (int i = 0; i < 4; i++) pv[i] = Ps[(ty * 4 + i) * 65 + kk];
#pragma unroll
            for (int j = 0; j < 4; j++) vv[j] = Vs[kk * 64 + tx * 4 + j];
#pragma unroll
            for (int i = 0; i < 4; i++)
#pragma unroll
                for (int j = 0; j < 4; j++)
                    oa[i][j] = fmaf(pv[i], vv[j], oa[i][j]);
        }
        __syncthreads();
    }

    float* ob = o + (size_t)b * Sv * Dv + (size_t)qt * 64 * Dv + h * HDv;
#pragma unroll
    for (int i = 0; i < 4; i++) {
        float inv_l = 1.0f / lrow[i];
#pragma unroll
        for (int j = 0; j < 4; j++)
            ob[(size_t)(ty * 4 + i) * Dv + tx * 4 + j] = oa[i][j] * inv_l;
    }
}

// ---------------------------------------------------------------------------
// Launch
// ---------------------------------------------------------------------------
extern "C" void kernel_launch(void* const* d_in, const int* in_sizes, int n_in,
                              void* d_out, int out_size)
{
    const float* x  = (const float*)d_in[0];
    const float* Wq = (const float*)d_in[1];
    const float* Wk = (const float*)d_in[2];
    const float* Wv = (const float*)d_in[3];
    const float* Wo = (const float*)d_in[4];
    const float* W1 = (const float*)d_in[5];
    const float* b1 = (const float*)d_in[6];
    const float* W2 = (const float*)d_in[7];
    const float* b2 = (const float*)d_in[8];
    float* out = (float*)d_out;

    float *q, *k, *v, *o, *x1, *hbuf;
    cudaGetSymbolAddress((void**)&q,    g_q);
    cudaGetSymbolAddress((void**)&k,    g_k);
    cudaGetSymbolAddress((void**)&v,    g_v);
    cudaGetSymbolAddress((void**)&o,    g_o);
    cudaGetSymbolAddress((void**)&x1,   g_x1);
    cudaGetSymbolAddress((void**)&hbuf, g_h);

    cudaFuncSetAttribute(attn_kern, cudaFuncAttributeMaxDynamicSharedMemorySize, ATTN_SMEM);

    const float scale = 0.21022410381342865f;  // 512^(-0.25)
    dim3 blk(256);
    dim3 gD (Dv  / 128, Mv / 128);   // (4, 64)
    dim3 gDE(DEv / 128, Mv / 128);   // (16, 64)

    // QKV projections (scale folded into q and k)
    gemm_mma<EP_NONE><<<gD, blk>>>(x, Wq, nullptr, nullptr, q, Mv, Dv, Dv, scale);
    gemm_mma<EP_NONE><<<gD, blk>>>(x, Wk, nullptr, nullptr, k, Mv, Dv, Dv, scale);
    gemm_mma<EP_NONE><<<gD, blk>>>(x, Wv, nullptr, nullptr, v, Mv, Dv, Dv, 1.0f);

    // Attention (fp32 SIMT)
    attn_kern<<<dim3(Sv / 64, Hv, Bv), blk, ATTN_SMEM>>>(q, k, v, o);

    // x1 = o @ Wo + x
    gemm_mma<EP_RES><<<gD, blk>>>(o, Wo, nullptr, x, x1, Mv, Dv, Dv, 1.0f);
    // h = gelu(x1 @ W1 + b1)
    gemm_mma<EP_BIAS_GELU><<<gDE, blk>>>(x1, W1, b1, nullptr, hbuf, Mv, DEv, Dv, 1.0f);
    // out = h @ W2 + b2 + x1
    gemm_mma<EP_BIAS_RES><<<gD, blk>>>(hbuf, W2, b2, x1, out, Mv, Dv, DEv, 1.0f);
}

// round 4
// speedup vs baseline: 2.8760x; 1.6273x over previous
#include <cuda_runtime.h>
#include <math.h>
#include <stdint.h>

// Problem constants
#define Bv   4
#define Sv   2048
#define Dv   512
#define Hv   8
#define Ev   4
#define HDv  64
#define Mv   (Bv * Sv)     // 8192
#define DEv  (Dv * Ev)     // 2048

// Scratch (device globals; no allocation allowed)
__device__ float g_q [Mv * Dv];
__device__ float g_k [Mv * Dv];
__device__ float g_v [Mv * Dv];
__device__ float g_o [Mv * Dv];
__device__ float g_x1[Mv * Dv];
__device__ float g_h [Mv * DEv];

enum { EP_NONE = 0, EP_RES = 1, EP_BIAS_GELU = 2, EP_BIAS_RES = 3 };

__device__ __forceinline__ float gelu_tanh(float x) {
    float x3 = x * x * x;
    float t = tanhf(0.7978845608028654f * (x + 0.044715f * x3));
    return 0.5f * x * (1.0f + t);
}

__device__ __forceinline__ uint32_t f2tf32(float x) {
    uint32_t r;
    asm("cvt.rna.tf32.f32 %0, %1;" : "=r"(r) : "f"(x));
    return r;
}

__device__ __forceinline__ void mma_tf32(float c[4], uint32_t a0, uint32_t a1,
                                         uint32_t a2, uint32_t a3,
                                         uint32_t b0, uint32_t b1) {
    asm volatile(
        "mma.sync.aligned.m16n8k8.row.col.f32.tf32.tf32.f32 "
        "{%0,%1,%2,%3}, {%4,%5,%6,%7}, {%8,%9}, {%0,%1,%2,%3};"
        : "+f"(c[0]), "+f"(c[1]), "+f"(c[2]), "+f"(c[3])
        : "r"(a0), "r"(a1), "r"(a2), "r"(a3), "r"(b0), "r"(b1));
}

// ---------------------------------------------------------------------------
// mma.sync tf32 GEMM (unchanged from round 3)
// ---------------------------------------------------------------------------
#define AS_STRIDE 20
#define BS_STRIDE 136

template <int EPI>
__global__ __launch_bounds__(256)
void gemm_mma(const float* __restrict__ A, const float* __restrict__ Bw,
              const float* __restrict__ bias, const float* __restrict__ res,
              float* __restrict__ C, int M, int N, int K, float alpha)
{
    __shared__ uint32_t As[128 * AS_STRIDE];
    __shared__ uint32_t Bs[16 * BS_STRIDE];

    const int tid = threadIdx.x;
    const int wid = tid >> 5;
    const int lid = tid & 31;
    const int gid = lid >> 2;
    const int tq  = lid & 3;
    const int wm  = (wid >> 1) * 32;
    const int wn  = (wid & 1) * 64;
    const int bm  = blockIdx.y * 128;
    const int bn  = blockIdx.x * 128;

    float acc[2][8][4];
#pragma unroll
    for (int mt = 0; mt < 2; mt++)
#pragma unroll
        for (int nt = 0; nt < 8; nt++)
#pragma unroll
            for (int u = 0; u < 4; u++) acc[mt][nt][u] = 0.0f;

    for (int k0 = 0; k0 < K; k0 += 16) {
#pragma unroll
        for (int it = 0; it < 2; it++) {
            int idx = it * 256 + tid;
            int r = idx >> 2;
            int c = (idx & 3) * 4;
            float4 v = *(const float4*)(A + (size_t)(bm + r) * K + k0 + c);
            uint32_t* dst = &As[r * AS_STRIDE + c];
            dst[0] = f2tf32(v.x); dst[1] = f2tf32(v.y);
            dst[2] = f2tf32(v.z); dst[3] = f2tf32(v.w);
        }
#pragma unroll
        for (int it = 0; it < 2; it++) {
            int idx = it * 256 + tid;
            int r = idx >> 5;
            int c = (idx & 31) * 4;
            float4 v = *(const float4*)(Bw + (size_t)(k0 + r) * N + bn + c);
            uint32_t* dst = &Bs[r * BS_STRIDE + c];
            dst[0] = f2tf32(v.x); dst[1] = f2tf32(v.y);
            dst[2] = f2tf32(v.z); dst[3] = f2tf32(v.w);
        }
        __syncthreads();

#pragma unroll
        for (int ks = 0; ks < 2; ks++) {
            uint32_t bfr[8][2];
#pragma unroll
            for (int nt = 0; nt < 8; nt++) {
                bfr[nt][0] = Bs[(ks * 8 + tq)     * BS_STRIDE + wn + nt * 8 + gid];
                bfr[nt][1] = Bs[(ks * 8 + tq + 4) * BS_STRIDE + wn + nt * 8 + gid];
            }
#pragma unroll
            for (int mt = 0; mt < 2; mt++) {
                const int r0 = wm + mt * 16 + gid;
                uint32_t a0 = As[r0       * AS_STRIDE + ks * 8 + tq];
                uint32_t a1 = As[(r0 + 8) * AS_STRIDE + ks * 8 + tq];
                uint32_t a2 = As[r0       * AS_STRIDE + ks * 8 + tq + 4];
                uint32_t a3 = As[(r0 + 8) * AS_STRIDE + ks * 8 + tq + 4];
#pragma unroll
                for (int nt = 0; nt < 8; nt++)
                    mma_tf32(acc[mt][nt], a0, a1, a2, a3, bfr[nt][0], bfr[nt][1]);
            }
        }
        __syncthreads();
    }

#pragma unroll
    for (int mt = 0; mt < 2; mt++) {
#pragma unroll
        for (int half = 0; half < 2; half++) {
            const int row = bm + wm + mt * 16 + gid + half * 8;
            float* Crow = C + (size_t)row * N;
            const float* rrow = (EPI == EP_RES || EPI == EP_BIAS_RES)
                                    ? (res + (size_t)row * N) : nullptr;
#pragma unroll
            for (int nt = 0; nt < 8; nt++) {
                const int col = bn + wn + nt * 8 + 2 * tq;
                float v0 = acc[mt][nt][half * 2 + 0] * alpha;
                float v1 = acc[mt][nt][half * 2 + 1] * alpha;
                if (EPI == EP_BIAS_GELU || EPI == EP_BIAS_RES) {
                    v0 += bias[col]; v1 += bias[col + 1];
                }
                if (EPI == EP_BIAS_GELU) { v0 = gelu_tanh(v0); v1 = gelu_tanh(v1); }
                if (EPI == EP_RES || EPI == EP_BIAS_RES) {
                    v0 += rrow[col]; v1 += rrow[col + 1];
                }
                *(float2*)(Crow + col) = make_float2(v0, v1);
            }
        }
    }
}

// ---------------------------------------------------------------------------
// Flash attention with mma.sync tf32.
// CTA: 128 q-rows of one (b,h). 8 warps x 16 q-rows. 64-key tiles, hd=64.
// SMEM: Ks[d=64][72] (K transposed, d-major), Vs[key=64][72] (natural),
//       Ps 8 warps x [16][68]. Q staged once at sm[0] ([128][72]) then held
//       as register A-fragments.
// ---------------------------------------------------------------------------
#define KS_STRIDE 72
#define PS_STRIDE 68
#define ATTN_SMEM ((2 * 64 * KS_STRIDE + 8 * 16 * PS_STRIDE) * (int)sizeof(float))

__global__ __launch_bounds__(256)
void attn_mma(const float* __restrict__ q, const float* __restrict__ k,
              const float* __restrict__ v, float* __restrict__ o)
{
    extern __shared__ float sm[];
    float* Ks = sm;                          // [64][72]  (Ks[d][key])
    float* Vs = sm + 64 * KS_STRIDE;         // [64][72]  (Vs[key][d])
    float* Ps = sm + 2 * 64 * KS_STRIDE;     // 8 x [16][68]

    const int tid = threadIdx.x;
    const int wid = tid >> 5;
    const int lid = tid & 31;
    const int gid = lid >> 2;      // 0..7
    const int tq  = lid & 3;       // 0..3
    const int qt  = blockIdx.x;    // 0..15
    const int h   = blockIdx.y;
    const int b   = blockIdx.z;

    const float* qb = q + ((size_t)b * Sv + qt * 128) * Dv + h * HDv;
    const float* kb = k + (size_t)b * Sv * Dv + h * HDv;
    const float* vb = v + (size_t)b * Sv * Dv + h * HDv;

    // ---- stage Q into sm[0..128*72) and grab register A-fragments ----
    float* Qstage = sm;
#pragma unroll
    for (int it = 0; it < 8; it++) {
        int idx = it * 256 + tid;       // 2048 float4
        int r = idx >> 4;
        int c = (idx & 15) * 4;
        float4 vq = *(const float4*)(qb + (size_t)r * Dv + c);
        float* dst = &Qstage[r * KS_STRIDE + c];
        dst[0] = vq.x; dst[1] = vq.y; dst[2] = vq.z; dst[3] = vq.w;
    }
    __syncthreads();

    uint32_t qf[8][4];
    {
        const int r0 = wid * 16 + gid;
#pragma unroll
        for (int ks = 0; ks < 8; ks++) {
            qf[ks][0] = __float_as_uint(Qstage[r0       * KS_STRIDE + ks * 8 + tq]);
            qf[ks][1] = __float_as_uint(Qstage[(r0 + 8) * KS_STRIDE + ks * 8 + tq]);
            qf[ks][2] = __float_as_uint(Qstage[r0       * KS_STRIDE + ks * 8 + tq + 4]);
            qf[ks][3] = __float_as_uint(Qstage[(r0 + 8) * KS_STRIDE + ks * 8 + tq + 4]);
        }
    }

    float oacc[8][4];
#pragma unroll
    for (int dt = 0; dt < 8; dt++)
#pragma unroll
        for (int u = 0; u < 4; u++) oacc[dt][u] = 0.0f;
    float mrow0 = -1e30f, mrow1 = -1e30f, lrow0 = 0.0f, lrow1 = 0.0f;
    float* Pw = Ps + wid * 16 * PS_STRIDE;

    for (int kt = 0; kt < Sv / 64; kt++) {
        __syncthreads();   // Qstage read done (kt=0) / prior-tile P@V done
        // K tile transposed: Ks[d][key]. thread: key=tid&63, cols c0..c0+15
        {
            int key = tid & 63, c0 = (tid >> 6) * 16;
            const float* kp = kb + (size_t)(kt * 64 + key) * Dv + c0;
#pragma unroll
            for (int j4 = 0; j4 < 4; j4++) {
                float4 vv = *(const float4*)(kp + j4 * 4);
                Ks[(c0 + j4 * 4 + 0) * KS_STRIDE + key] = vv.x;
                Ks[(c0 + j4 * 4 + 1) * KS_STRIDE + key] = vv.y;
                Ks[(c0 + j4 * 4 + 2) * KS_STRIDE + key] = vv.z;
                Ks[(c0 + j4 * 4 + 3) * KS_STRIDE + key] = vv.w;
            }
        }
        // V tile natural: Vs[key][d]
#pragma unroll
        for (int it = 0; it < 4; it++) {
            int idx = it * 256 + tid;
            int r = idx >> 4;
            int c = (idx & 15) * 4;
            float4 vv = *(const float4*)(vb + (size_t)(kt * 64 + r) * Dv + c);
            float* dst = &Vs[r * KS_STRIDE + c];
            dst[0] = vv.x; dst[1] = vv.y; dst[2] = vv.z; dst[3] = vv.w;
        }
        __syncthreads();

        // ---- S = Q @ K^T : warp computes 16 x 64 ----
        float sacc[8][4];
#pragma unroll
        for (int nt = 0; nt < 8; nt++)
#pragma unroll
            for (int u = 0; u < 4; u++) sacc[nt][u] = 0.0f;
#pragma unroll
        for (int ks = 0; ks < 8; ks++) {
#pragma unroll
            for (int nt = 0; nt < 8; nt++) {
                uint32_t b0 = __float_as_uint(Ks[(ks * 8 + tq)     * KS_STRIDE + nt * 8 + gid]);
                uint32_t b1 = __float_as_uint(Ks[(ks * 8 + tq + 4) * KS_STRIDE + nt * 8 + gid]);
                mma_tf32(sacc[nt], qf[ks][0], qf[ks][1], qf[ks][2], qf[ks][3], b0, b1);
            }
        }

        // ---- online softmax on fragments (rows gid, gid+8) ----
        float mx0 = -1e30f, mx1 = -1e30f;
#pragma unroll
        for (int nt = 0; nt < 8; nt++) {
            mx0 = fmaxf(mx0, fmaxf(sacc[nt][0], sacc[nt][1]));
            mx1 = fmaxf(mx1, fmaxf(sacc[nt][2], sacc[nt][3]));
        }
        mx0 = fmaxf(mx0, __shfl_xor_sync(0xffffffffu, mx0, 1));
        mx0 = fmaxf(mx0, __shfl_xor_sync(0xffffffffu, mx0, 2));
        mx1 = fmaxf(mx1, __shfl_xor_sync(0xffffffffu, mx1, 1));
        mx1 = fmaxf(mx1, __shfl_xor_sync(0xffffffffu, mx1, 2));
        float mn0 = fmaxf(mrow0, mx0), mn1 = fmaxf(mrow1, mx1);
        float corr0 = __expf(mrow0 - mn0), corr1 = __expf(mrow1 - mn1);
        float ps0 = 0.0f, ps1 = 0.0f;
#pragma unroll
        for (int nt = 0; nt < 8; nt++) {
            sacc[nt][0] = __expf(sacc[nt][0] - mn0);
            sacc[nt][1] = __expf(sacc[nt][1] - mn0);
            sacc[nt][2] = __expf(sacc[nt][2] - mn1);
            sacc[nt][3] = __expf(sacc[nt][3] - mn1);
            ps0 += sacc[nt][0] + sacc[nt][1];
            ps1 += sacc[nt][2] + sacc[nt][3];
        }
        ps0 += __shfl_xor_sync(0xffffffffu, ps0, 1);
        ps0 += __shfl_xor_sync(0xffffffffu, ps0, 2);
        ps1 += __shfl_xor_sync(0xffffffffu, ps1, 1);
        ps1 += __shfl_xor_sync(0xffffffffu, ps1, 2);
        lrow0 = lrow0 * corr0 + ps0;
        lrow1 = lrow1 * corr1 + ps1;
        mrow0 = mn0; mrow1 = mn1;
#pragma unroll
        for (int dt = 0; dt < 8; dt++) {
            oacc[dt][0] *= corr0; oacc[dt][1] *= corr0;
            oacc[dt][2] *= corr1; oacc[dt][3] *= corr1;
        }

        // ---- route P through per-warp SMEM for re-fragmentation ----
#pragma unroll
        for (int nt = 0; nt < 8; nt++) {
            *(float2*)&Pw[gid       * PS_STRIDE + nt * 8 + 2 * tq] =
                make_float2(sacc[nt][0], sacc[nt][1]);
            *(float2*)&Pw[(gid + 8) * PS_STRIDE + nt * 8 + 2 * tq] =
                make_float2(sacc[nt][2], sacc[nt][3]);
        }
        __syncwarp();

        // ---- O += P @ V ----
#pragma unroll
        for (int ks = 0; ks < 8; ks++) {
            uint32_t a0 = __float_as_uint(Pw[gid       * PS_STRIDE + ks * 8 + tq]);
            uint32_t a1 = __float_as_uint(Pw[(gid + 8) * PS_STRIDE + ks * 8 + tq]);
            uint32_t a2 = __float_as_uint(Pw[gid       * PS_STRIDE + ks * 8 + tq + 4]);
            uint32_t a3 = __float_as_uint(Pw[(gid + 8) * PS_STRIDE + ks * 8 + tq + 4]);
#pragma unroll
            for (int dt = 0; dt < 8; dt++) {
                uint32_t b0 = __float_as_uint(Vs[(ks * 8 + tq)     * KS_STRIDE + dt * 8 + gid]);
                uint32_t b1 = __float_as_uint(Vs[(ks * 8 + tq + 4) * KS_STRIDE + dt * 8 + gid]);
                mma_tf32(oacc[dt], a0, a1, a2, a3, b0, b1);
            }
        }
        __syncwarp();
    }

    // ---- normalize and write O ----
    float inv0 = 1.0f / lrow0, inv1 = 1.0f / lrow1;
    float* ob = o + ((size_t)b * Sv + qt * 128 + wid * 16) * Dv + h * HDv;
#pragma unroll
    for (int dt = 0; dt < 8; dt++) {
        int col = dt * 8 + 2 * tq;
        *(float2*)(ob + (size_t)gid * Dv + col) =
            make_float2(oacc[dt][0] * inv0, oacc[dt][1] * inv0);
        *(float2*)(ob + (size_t)(gid + 8) * Dv + col) =
            make_float2(oacc[dt][2] * inv1, oacc[dt][3] * inv1);
    }
}

// ---------------------------------------------------------------------------
// Launch
// ---------------------------------------------------------------------------
extern "C" void kernel_launch(void* const* d_in, const int* in_sizes, int n_in,
                              void* d_out, int out_size)
{
    const float* x  = (const float*)d_in[0];
    const float* Wq = (const float*)d_in[1];
    const float* Wk = (const float*)d_in[2];
    const float* Wv = (const float*)d_in[3];
    const float* Wo = (const float*)d_in[4];
    const float* W1 = (const float*)d_in[5];
    const float* b1 = (const float*)d_in[6];
    const float* W2 = (const float*)d_in[7];
    const float* b2 = (const float*)d_in[8];
    float* out = (float*)d_out;

    float *q, *k, *v, *o, *x1, *hbuf;
    cudaGetSymbolAddress((void**)&q,    g_q);
    cudaGetSymbolAddress((void**)&k,    g_k);
    cudaGetSymbolAddress((void**)&v,    g_v);
    cudaGetSymbolAddress((void**)&o,    g_o);
    cudaGetSymbolAddress((void**)&x1,   g_x1);
    cudaGetSymbolAddress((void**)&hbuf, g_h);

    cudaFuncSetAttribute(attn_mma, cudaFuncAttributeMaxDynamicSharedMemorySize, ATTN_SMEM);

    const float scale = 0.21022410381342865f;  // 512^(-0.25)
    dim3 blk(256);
    dim3 gD (Dv  / 128, Mv / 128);   // (4, 64)
    dim3 gDE(DEv / 128, Mv / 128);   // (16, 64)

    gemm_mma<EP_NONE><<<gD, blk>>>(x, Wq, nullptr, nullptr, q, Mv, Dv, Dv, scale);
    gemm_mma<EP_NONE><<<gD, blk>>>(x, Wk, nullptr, nullptr, k, Mv, Dv, Dv, scale);
    gemm_mma<EP_NONE><<<gD, blk>>>(x, Wv, nullptr, nullptr, v, Mv, Dv, Dv, 1.0f);

    attn_mma<<<dim3(Sv / 128, Hv, Bv), blk, ATTN_SMEM>>>(q, k, v, o);

    gemm_mma<EP_RES><<<gD, blk>>>(o, Wo, nullptr, x, x1, Mv, Dv, Dv, 1.0f);
    gemm_mma<EP_BIAS_GELU><<<gDE, blk>>>(x1, W1, b1, nullptr, hbuf, Mv, DEv, Dv, 1.0f);
    gemm_mma<EP_BIAS_RES><<<gD, blk>>>(hbuf, W2, b2, x1, out, Mv, Dv, DEv, 1.0f);
}

// round 5
// speedup vs baseline: 3.4954x; 1.2154x over previous
#include <cuda_runtime.h>
#include <math.h>
#include <stdint.h>

// Problem constants
#define Bv   4
#define Sv   2048
#define Dv   512
#define Hv   8
#define Ev   4
#define HDv  64
#define Mv   (Bv * Sv)     // 8192
#define DEv  (Dv * Ev)     // 2048

// Scratch (device globals; no allocation allowed)
__device__ float g_q [Mv * Dv];
__device__ float g_k [Mv * Dv];
__device__ float g_v [Mv * Dv];
__device__ float g_o [Mv * Dv];
__device__ float g_x1[Mv * Dv];
__device__ float g_h [Mv * DEv];

enum { EP_NONE = 0, EP_RES = 1, EP_BIAS_GELU = 2, EP_BIAS_RES = 3 };

__device__ __forceinline__ float gelu_tanh(float x) {
    float x3 = x * x * x;
    float t = tanhf(0.7978845608028654f * (x + 0.044715f * x3));
    return 0.5f * x * (1.0f + t);
}

__device__ __forceinline__ uint32_t smem_u32(const void* p) {
    uint32_t a;
    asm("{ .reg .u64 t; cvta.to.shared.u64 t, %1; cvt.u32.u64 %0, t; }"
        : "=r"(a) : "l"(p));
    return a;
}

#define CP_ASYNC16(dst, src) \
    asm volatile("cp.async.cg.shared.global [%0], [%1], 16;" :: "r"(dst), "l"(src))
#define CP_COMMIT() asm volatile("cp.async.commit_group;" ::: "memory")
#define CP_WAIT(n)  asm volatile("cp.async.wait_group %0;" :: "n"(n) : "memory")

__device__ __forceinline__ void mma_tf32(float c[4], uint32_t a0, uint32_t a1,
                                         uint32_t a2, uint32_t a3,
                                         uint32_t b0, uint32_t b1) {
    asm volatile(
        "mma.sync.aligned.m16n8k8.row.col.f32.tf32.tf32.f32 "
        "{%0,%1,%2,%3}, {%4,%5,%6,%7}, {%8,%9}, {%0,%1,%2,%3};"
        : "+f"(c[0]), "+f"(c[1]), "+f"(c[2]), "+f"(c[3])
        : "r"(a0), "r"(a1), "r"(a2), "r"(a3), "r"(b0), "r"(b1));
}

// ---------------------------------------------------------------------------
// cp.async double-buffered mma.sync tf32 GEMM: C = epilogue(alpha * A @ B)
// A: [M,K] row-major fp32, B: [K,N] row-major fp32 (raw fp32 bits fed as tf32).
// CTA 128x128, BK=32, 256 threads, warp grid 4(M)x2(N), warp tile 32x64.
// ---------------------------------------------------------------------------
#define AS_STRIDE 36
#define BS_STRIDE 136
#define AS_BUF (128 * AS_STRIDE)          // floats per A stage
#define BS_BUF (32 * BS_STRIDE)           // floats per B stage
#define GEMM_SMEM ((2 * AS_BUF + 2 * BS_BUF) * (int)sizeof(float))

template <int EPI>
__global__ __launch_bounds__(256)
void gemm_mma(const float* __restrict__ A, const float* __restrict__ Bw,
              const float* __restrict__ bias, const float* __restrict__ res,
              float* __restrict__ C, int M, int N, int K, float alpha)
{
    extern __shared__ float smf[];
    float* Asb = smf;                   // 2 x AS_BUF
    float* Bsb = smf + 2 * AS_BUF;      // 2 x BS_BUF

    const int tid = threadIdx.x;
    const int wid = tid >> 5;
    const int lid = tid & 31;
    const int gid = lid >> 2;
    const int tq  = lid & 3;
    const int wm  = (wid >> 1) * 32;
    const int wn  = (wid & 1) * 64;
    const int bm  = blockIdx.y * 128;
    const int bn  = blockIdx.x * 128;
    const int NS  = K >> 5;

    // cp.async target addresses (per-thread fixed pattern)
    // A: 1024 float4 per stage -> 4 per thread; r = idx>>3, c = (idx&7)*4
    // B: 1024 float4 per stage -> 4 per thread; r = idx>>5, c = (idx&31)*4
    auto issue_stage = [&](int s, int buf) {
        float* ab = Asb + buf * AS_BUF;
        float* bb = Bsb + buf * BS_BUF;
        const float* Ap = A + (size_t)bm * K + s * 32;
        const float* Bp = Bw + (size_t)(s * 32) * N + bn;
#pragma unroll
        for (int it = 0; it < 4; it++) {
            int idx = it * 256 + tid;
            int r = idx >> 3, c = (idx & 7) * 4;
            CP_ASYNC16(smem_u32(ab + r * AS_STRIDE + c), Ap + (size_t)r * K + c);
        }
#pragma unroll
        for (int it = 0; it < 4; it++) {
            int idx = it * 256 + tid;
            int r = idx >> 5, c = (idx & 31) * 4;
            CP_ASYNC16(smem_u32(bb + r * BS_STRIDE + c), Bp + (size_t)r * N + c);
        }
        CP_COMMIT();
    };

    float acc[2][8][4];
#pragma unroll
    for (int mt = 0; mt < 2; mt++)
#pragma unroll
        for (int nt = 0; nt < 8; nt++)
#pragma unroll
            for (int u = 0; u < 4; u++) acc[mt][nt][u] = 0.0f;

    issue_stage(0, 0);

    for (int s = 0; s < NS; s++) {
        const int buf = s & 1;
        if (s + 1 < NS) {
            issue_stage(s + 1, 1 - buf);
            CP_WAIT(1);
        } else {
            CP_WAIT(0);
        }
        __syncthreads();

        const uint32_t* As = (const uint32_t*)(Asb + buf * AS_BUF);
        const uint32_t* Bs = (const uint32_t*)(Bsb + buf * BS_BUF);
#pragma unroll
        for (int ks = 0; ks < 4; ks++) {
            uint32_t bfr[8][2];
#pragma unroll
            for (int nt = 0; nt < 8; nt++) {
                bfr[nt][0] = Bs[(ks * 8 + tq)     * BS_STRIDE + wn + nt * 8 + gid];
                bfr[nt][1] = Bs[(ks * 8 + tq + 4) * BS_STRIDE + wn + nt * 8 + gid];
            }
#pragma unroll
            for (int mt = 0; mt < 2; mt++) {
                const int r0 = wm + mt * 16 + gid;
                uint32_t a0 = As[r0       * AS_STRIDE + ks * 8 + tq];
                uint32_t a1 = As[(r0 + 8) * AS_STRIDE + ks * 8 + tq];
                uint32_t a2 = As[r0       * AS_STRIDE + ks * 8 + tq + 4];
                uint32_t a3 = As[(r0 + 8) * AS_STRIDE + ks * 8 + tq + 4];
#pragma unroll
                for (int nt = 0; nt < 8; nt++)
                    mma_tf32(acc[mt][nt], a0, a1, a2, a3, bfr[nt][0], bfr[nt][1]);
            }
        }
        __syncthreads();
    }

    // Epilogue
#pragma unroll
    for (int mt = 0; mt < 2; mt++) {
#pragma unroll
        for (int half = 0; half < 2; half++) {
            const int row = bm + wm + mt * 16 + gid + half * 8;
            float* Crow = C + (size_t)row * N;
            const float* rrow = (EPI == EP_RES || EPI == EP_BIAS_RES)
                                    ? (res + (size_t)row * N) : nullptr;
#pragma unroll
            for (int nt = 0; nt < 8; nt++) {
                const int col = bn + wn + nt * 8 + 2 * tq;
                float v0 = acc[mt][nt][half * 2 + 0] * alpha;
                float v1 = acc[mt][nt][half * 2 + 1] * alpha;
                if (EPI == EP_BIAS_GELU || EPI == EP_BIAS_RES) {
                    v0 += bias[col]; v1 += bias[col + 1];
                }
                if (EPI == EP_BIAS_GELU) { v0 = gelu_tanh(v0); v1 = gelu_tanh(v1); }
                if (EPI == EP_RES || EPI == EP_BIAS_RES) {
                    v0 += rrow[col]; v1 += rrow[col + 1];
                }
                *(float2*)(Crow + col) = make_float2(v0, v1);
            }
        }
    }
}

// ---------------------------------------------------------------------------
// Flash attention with mma.sync tf32 (unchanged from round 4)
// ---------------------------------------------------------------------------
#define KS_STRIDE 72
#define PS_STRIDE 68
#define ATTN_SMEM ((2 * 64 * KS_STRIDE + 8 * 16 * PS_STRIDE) * (int)sizeof(float))

__global__ __launch_bounds__(256)
void attn_mma(const float* __restrict__ q, const float* __restrict__ k,
              const float* __restrict__ v, float* __restrict__ o)
{
    extern __shared__ float sm[];
    float* Ks = sm;
    float* Vs = sm + 64 * KS_STRIDE;
    float* Ps = sm + 2 * 64 * KS_STRIDE;

    const int tid = threadIdx.x;
    const int wid = tid >> 5;
    const int lid = tid & 31;
    const int gid = lid >> 2;
    const int tq  = lid & 3;
    const int qt  = blockIdx.x;
    const int h   = blockIdx.y;
    const int b   = blockIdx.z;

    const float* qb = q + ((size_t)b * Sv + qt * 128) * Dv + h * HDv;
    const float* kb = k + (size_t)b * Sv * Dv + h * HDv;
    const float* vb = v + (size_t)b * Sv * Dv + h * HDv;

    float* Qstage = sm;
#pragma unroll
    for (int it = 0; it < 8; it++) {
        int idx = it * 256 + tid;
        int r = idx >> 4;
        int c = (idx & 15) * 4;
        float4 vq = *(const float4*)(qb + (size_t)r * Dv + c);
        float* dst = &Qstage[r * KS_STRIDE + c];
        dst[0] = vq.x; dst[1] = vq.y; dst[2] = vq.z; dst[3] = vq.w;
    }
    __syncthreads();

    uint32_t qf[8][4];
    {
        const int r0 = wid * 16 + gid;
#pragma unroll
        for (int ks = 0; ks < 8; ks++) {
            qf[ks][0] = __float_as_uint(Qstage[r0       * KS_STRIDE + ks * 8 + tq]);
            qf[ks][1] = __float_as_uint(Qstage[(r0 + 8) * KS_STRIDE + ks * 8 + tq]);
            qf[ks][2] = __float_as_uint(Qstage[r0       * KS_STRIDE + ks * 8 + tq + 4]);
            qf[ks][3] = __float_as_uint(Qstage[(r0 + 8) * KS_STRIDE + ks * 8 + tq + 4]);
        }
    }

    float oacc[8][4];
#pragma unroll
    for (int dt = 0; dt < 8; dt++)
#pragma unroll
        for (int u = 0; u < 4; u++) oacc[dt][u] = 0.0f;
    float mrow0 = -1e30f, mrow1 = -1e30f, lrow0 = 0.0f, lrow1 = 0.0f;
    float* Pw = Ps + wid * 16 * PS_STRIDE;

    for (int kt = 0; kt < Sv / 64; kt++) {
        __syncthreads();
        {
            int key = tid & 63, c0 = (tid >> 6) * 16;
            const float* kp = kb + (size_t)(kt * 64 + key) * Dv + c0;
#pragma unroll
            for (int j4 = 0; j4 < 4; j4++) {
                float4 vv = *(const float4*)(kp + j4 * 4);
                Ks[(c0 + j4 * 4 + 0) * KS_STRIDE + key] = vv.x;
                Ks[(c0 + j4 * 4 + 1) * KS_STRIDE + key] = vv.y;
                Ks[(c0 + j4 * 4 + 2) * KS_STRIDE + key] = vv.z;
                Ks[(c0 + j4 * 4 + 3) * KS_STRIDE + key] = vv.w;
            }
        }
#pragma unroll
        for (int it = 0; it < 4; it++) {
            int idx = it * 256 + tid;
            int r = idx >> 4;
            int c = (idx & 15) * 4;
            float4 vv = *(const float4*)(vb + (size_t)(kt * 64 + r) * Dv + c);
            float* dst = &Vs[r * KS_STRIDE + c];
            dst[0] = vv.x; dst[1] = vv.y; dst[2] = vv.z; dst[3] = vv.w;
        }
        __syncthreads();

        float sacc[8][4];
#pragma unroll
        for (int nt = 0; nt < 8; nt++)
#pragma unroll
            for (int u = 0; u < 4; u++) sacc[nt][u] = 0.0f;
#pragma unroll
        for (int ks = 0; ks < 8; ks++) {
#pragma unroll
            for (int nt = 0; nt < 8; nt++) {
                uint32_t b0 = __float_as_uint(Ks[(ks * 8 + tq)     * KS_STRIDE + nt * 8 + gid]);
                uint32_t b1 = __float_as_uint(Ks[(ks * 8 + tq + 4) * KS_STRIDE + nt * 8 + gid]);
                mma_tf32(sacc[nt], qf[ks][0], qf[ks][1], qf[ks][2], qf[ks][3], b0, b1);
            }
        }

        float mx0 = -1e30f, mx1 = -1e30f;
#pragma unroll
        for (int nt = 0; nt < 8; nt++) {
            mx0 = fmaxf(mx0, fmaxf(sacc[nt][0], sacc[nt][1]));
            mx1 = fmaxf(mx1, fmaxf(sacc[nt][2], sacc[nt][3]));
        }
        mx0 = fmaxf(mx0, __shfl_xor_sync(0xffffffffu, mx0, 1));
        mx0 = fmaxf(mx0, __shfl_xor_sync(0xffffffffu, mx0, 2));
        mx1 = fmaxf(mx1, __shfl_xor_sync(0xffffffffu, mx1, 1));
        mx1 = fmaxf(mx1, __shfl_xor_sync(0xffffffffu, mx1, 2));
        float mn0 = fmaxf(mrow0, mx0), mn1 = fmaxf(mrow1, mx1);
        float corr0 = __expf(mrow0 - mn0), corr1 = __expf(mrow1 - mn1);
        float ps0 = 0.0f, ps1 = 0.0f;
#pragma unroll
        for (int nt = 0; nt < 8; nt++) {
            sacc[nt][0] = __expf(sacc[nt][0] - mn0);
            sacc[nt][1] = __expf(sacc[nt][1] - mn0);
            sacc[nt][2] = __expf(sacc[nt][2] - mn1);
            sacc[nt][3] = __expf(sacc[nt][3] - mn1);
            ps0 += sacc[nt][0] + sacc[nt][1];
            ps1 += sacc[nt][2] + sacc[nt][3];
        }
        ps0 += __shfl_xor_sync(0xffffffffu, ps0, 1);
        ps0 += __shfl_xor_sync(0xffffffffu, ps0, 2);
        ps1 += __shfl_xor_sync(0xffffffffu, ps1, 1);
        ps1 += __shfl_xor_sync(0xffffffffu, ps1, 2);
        lrow0 = lrow0 * corr0 + ps0;
        lrow1 = lrow1 * corr1 + ps1;
        mrow0 = mn0; mrow1 = mn1;
#pragma unroll
        for (int dt = 0; dt < 8; dt++) {
            oacc[dt][0] *= corr0; oacc[dt][1] *= corr0;
            oacc[dt][2] *= corr1; oacc[dt][3] *= corr1;
        }

#pragma unroll
        for (int nt = 0; nt < 8; nt++) {
            *(float2*)&Pw[gid       * PS_STRIDE + nt * 8 + 2 * tq] =
                make_float2(sacc[nt][0], sacc[nt][1]);
            *(float2*)&Pw[(gid + 8) * PS_STRIDE + nt * 8 + 2 * tq] =
                make_float2(sacc[nt][2], sacc[nt][3]);
        }
        __syncwarp();

#pragma unroll
        for (int ks = 0; ks < 8; ks++) {
            uint32_t a0 = __float_as_uint(Pw[gid       * PS_STRIDE + ks * 8 + tq]);
            uint32_t a1 = __float_as_uint(Pw[(gid + 8) * PS_STRIDE + ks * 8 + tq]);
            uint32_t a2 = __float_as_uint(Pw[gid       * PS_STRIDE + ks * 8 + tq + 4]);
            uint32_t a3 = __float_as_uint(Pw[(gid + 8) * PS_STRIDE + ks * 8 + tq + 4]);
#pragma unroll
            for (int dt = 0; dt < 8; dt++) {
                uint32_t b0 = __float_as_uint(Vs[(ks * 8 + tq)     * KS_STRIDE + dt * 8 + gid]);
                uint32_t b1 = __float_as_uint(Vs[(ks * 8 + tq + 4) * KS_STRIDE + dt * 8 + gid]);
                mma_tf32(oacc[dt], a0, a1, a2, a3, b0, b1);
            }
        }
        __syncwarp();
    }

    float inv0 = 1.0f / lrow0, inv1 = 1.0f / lrow1;
    float* ob = o + ((size_t)b * Sv + qt * 128 + wid * 16) * Dv + h * HDv;
#pragma unroll
    for (int dt = 0; dt < 8; dt++) {
        int col = dt * 8 + 2 * tq;
        *(float2*)(ob + (size_t)gid * Dv + col) =
            make_float2(oacc[dt][0] * inv0, oacc[dt][1] * inv0);
        *(float2*)(ob + (size_t)(gid + 8) * Dv + col) =
            make_float2(oacc[dt][2] * inv1, oacc[dt][3] * inv1);
    }
}

// ---------------------------------------------------------------------------
// Launch
// ---------------------------------------------------------------------------
extern "C" void kernel_launch(void* const* d_in, const int* in_sizes, int n_in,
                              void* d_out, int out_size)
{
    const float* x  = (const float*)d_in[0];
    const float* Wq = (const float*)d_in[1];
    const float* Wk = (const float*)d_in[2];
    const float* Wv = (const float*)d_in[3];
    const float* Wo = (const float*)d_in[4];
    const float* W1 = (const float*)d_in[5];
    const float* b1 = (const float*)d_in[6];
    const float* W2 = (const float*)d_in[7];
    const float* b2 = (const float*)d_in[8];
    float* out = (float*)d_out;

    float *q, *k, *v, *o, *x1, *hbuf;
    cudaGetSymbolAddress((void**)&q,    g_q);
    cudaGetSymbolAddress((void**)&k,    g_k);
    cudaGetSymbolAddress((void**)&v,    g_v);
    cudaGetSymbolAddress((void**)&o,    g_o);
    cudaGetSymbolAddress((void**)&x1,   g_x1);
    cudaGetSymbolAddress((void**)&hbuf, g_h);

    cudaFuncSetAttribute(gemm_mma<EP_NONE>,      cudaFuncAttributeMaxDynamicSharedMemorySize, GEMM_SMEM);
    cudaFuncSetAttribute(gemm_mma<EP_RES>,       cudaFuncAttributeMaxDynamicSharedMemorySize, GEMM_SMEM);
    cudaFuncSetAttribute(gemm_mma<EP_BIAS_GELU>, cudaFuncAttributeMaxDynamicSharedMemorySize, GEMM_SMEM);
    cudaFuncSetAttribute(gemm_mma<EP_BIAS_RES>,  cudaFuncAttributeMaxDynamicSharedMemorySize, GEMM_SMEM);
    cudaFuncSetAttribute(attn_mma, cudaFuncAttributeMaxDynamicSharedMemorySize, ATTN_SMEM);

    const float scale = 0.21022410381342865f;  // 512^(-0.25)
    dim3 blk(256);
    dim3 gD (Dv  / 128, Mv / 128);   // (4, 64)
    dim3 gDE(DEv / 128, Mv / 128);   // (16, 64)

    gemm_mma<EP_NONE><<<gD, blk, GEMM_SMEM>>>(x, Wq, nullptr, nullptr, q, Mv, Dv, Dv, scale);
    gemm_mma<EP_NONE><<<gD, blk, GEMM_SMEM>>>(x, Wk, nullptr, nullptr, k, Mv, Dv, Dv, scale);
    gemm_mma<EP_NONE><<<gD, blk, GEMM_SMEM>>>(x, Wv, nullptr, nullptr, v, Mv, Dv, Dv, 1.0f);

    attn_mma<<<dim3(Sv / 128, Hv, Bv), blk, ATTN_SMEM>>>(q, k, v, o);

    gemm_mma<EP_RES><<<gD, blk, GEMM_SMEM>>>(o, Wo, nullptr, x, x1, Mv, Dv, Dv, 1.0f);
    gemm_mma<EP_BIAS_GELU><<<gDE, blk, GEMM_SMEM>>>(x1, W1, b1, nullptr, hbuf, Mv, DEv, Dv, 1.0f);
    gemm_mma<EP_BIAS_RES><<<gD, blk, GEMM_SMEM>>>(hbuf, W2, b2, x1, out, Mv, Dv, DEv, 1.0f);
}